// round 6
// baseline (speedup 1.0000x reference)
#include <cuda_runtime.h>
#include <cstddef>

#define B_      128
#define NNZ_    128
#define H_      128
#define KOUT_   4096
#define FDIM_   135909

#define L2_GRID   888            // 148 SMs * 6 blocks
#define CHUNKS    2048           // (B*KOUT) / 256 outputs per chunk

// Intermediate val1 [B, H] — device global scratch (no allocations allowed).
__device__ float g_val1[B_ * H_];

// ---------------------------------------------------------------------------
// Layer 1: val1[b,h] = relu( sum_i v[b,i] * W1[h, fidx[b,i]] + b1[h] )
// Warp per (b,h); lane gathers 4 W1 elements, butterfly reduce. This phase is
// at the random-32B-sector HBM floor (~17.6us) — leave it alone.
// ---------------------------------------------------------------------------
__global__ __launch_bounds__(256) void layer1_kernel(
    const float* __restrict__ inv,
    const int*   __restrict__ fidx,
    const float* __restrict__ W1,
    const float* __restrict__ b1)
{
    const int tid  = threadIdx.x;
    const int warp = tid >> 5;
    const int lane = tid & 31;
    const int b    = blockIdx.x >> 4;
    const int h    = ((blockIdx.x & 15) << 3) + warp;

    __shared__ int   sidx[NNZ_];
    __shared__ float sval[NNZ_];
    if (tid < 128) sidx[tid]       = fidx[(b << 7) + tid];
    else           sval[tid - 128] = inv [(b << 7) + tid - 128];
    __syncthreads();

    const float* w = W1 + (size_t)h * FDIM_;
    const int4   i4 = reinterpret_cast<const int4*>(sidx)[lane];
    const float4 v4 = reinterpret_cast<const float4*>(sval)[lane];

    float acc = __ldg(w + i4.x) * v4.x + __ldg(w + i4.y) * v4.y +
                __ldg(w + i4.z) * v4.z + __ldg(w + i4.w) * v4.w;

    #pragma unroll
    for (int o = 16; o > 0; o >>= 1)
        acc += __shfl_xor_sync(0xffffffffu, acc, o);

    if (lane == 0)
        g_val1[(b << 7) + h] = fmaxf(acc + __ldg(b1 + h), 0.0f);
}

// ---------------------------------------------------------------------------
// Layer 2 (persistent, software-pipelined):
//   val2[b,k] = <val1[b,:], W2[lab[b,k],:]> + b2[lab[b,k]]
// Grid = 888 blocks (6/SM), grid-striding over 2048 chunks of 256 outputs.
// Per chunk: labels staged in smem (removes the lab->row dependency chain),
// val1[b] staged in smem. Each warp handles 8 pipelined groups of 4 outputs:
//   iter g: dot(wv_g, sv)  ->  issue loads for group g+1  ->  shfl-reduce g
// so 4 coalesced 512B row-loads are in flight ~continuously per warp
// (R1 duty cycle was ~70%; no block churn, no repeated prologues).
// ---------------------------------------------------------------------------
__global__ __launch_bounds__(256, 6) void layer2_kernel(
    const int*   __restrict__ lab,
    const float* __restrict__ W2,
    const float* __restrict__ b2,
    float*       __restrict__ out,
    float*       __restrict__ out_lab)   // may be null
{
    const int warp = threadIdx.x >> 5;
    const int lane = threadIdx.x & 31;

    __shared__ float4 s4[32];
    __shared__ int    slab[256];

    const float4* __restrict__ W2v = reinterpret_cast<const float4*>(W2);

    for (int c = blockIdx.x; c < CHUNKS; c += L2_GRID) {
        const int b    = c >> 4;
        const int base = (b << 12) + ((c & 15) << 8);   // first output index

        __syncthreads();                                // protect smem reuse
        if (threadIdx.x < 32)
            s4[threadIdx.x] =
                reinterpret_cast<const float4*>(g_val1 + (b << 7))[threadIdx.x];
        slab[threadIdx.x] = lab[base + threadIdx.x];
        __syncthreads();

        const float4 sv = s4[lane];

        int koff = warp << 2;                           // within-chunk offset

        // pipeline prologue: group 0
        int rows[4];
        #pragma unroll
        for (int j = 0; j < 4; j++) rows[j] = slab[koff + j];
        float4 wv[4];
        #pragma unroll
        for (int j = 0; j < 4; j++)
            wv[j] = __ldg(W2v + ((size_t)rows[j] << 5) + lane);
        float bias = (lane < 4) ? __ldg(b2 + rows[lane]) : 0.0f;

        #pragma unroll
        for (int g = 0; g < 8; g++) {
            // consume current loads
            float acc[4];
            #pragma unroll
            for (int j = 0; j < 4; j++)
                acc[j] = wv[j].x * sv.x + wv[j].y * sv.y +
                         wv[j].z * sv.z + wv[j].w * sv.w;

            // issue next group's loads before the reduce
            int   nrows[4] = {0, 0, 0, 0};
            float nbias    = 0.0f;
            if (g < 7) {
                const int nkoff = koff + 32;
                #pragma unroll
                for (int j = 0; j < 4; j++) nrows[j] = slab[nkoff + j];
                #pragma unroll
                for (int j = 0; j < 4; j++)
                    wv[j] = __ldg(W2v + ((size_t)nrows[j] << 5) + lane);
                if (lane < 4) nbias = __ldg(b2 + nrows[lane]);
            }

            // reduce current group while next loads are in flight
            #pragma unroll
            for (int j = 0; j < 4; j++) {
                #pragma unroll
                for (int o = 16; o > 0; o >>= 1)
                    acc[j] += __shfl_xor_sync(0xffffffffu, acc[j], o);
            }

            if (lane < 4) {
                out[base + koff + lane] = acc[lane] + bias;
                if (out_lab) out_lab[base + koff + lane] = (float)rows[lane];
            }

            #pragma unroll
            for (int j = 0; j < 4; j++) rows[j] = nrows[j];
            bias = nbias;
            koff += 32;
        }
    }
}

// ---------------------------------------------------------------------------
extern "C" void kernel_launch(void* const* d_in, const int* in_sizes, int n_in,
                              void* d_out, int out_size)
{
    const float* inv  = (const float*)d_in[0];   // in_values        [B, NNZ]
    const int*   fidx = (const int*)  d_in[1];   // active_in_indices[B, NNZ]
    const int*   lab  = (const int*)  d_in[2];   // active_label_idx [B, KOUT]
    const float* W1   = (const float*)d_in[3];   // [H, FDIM]
    const float* b1   = (const float*)d_in[4];   // [H]
    const float* W2   = (const float*)d_in[5];   // [C, H]
    const float* b2   = (const float*)d_in[6];   // [C]

    float* out = (float*)d_out;
    const int n_val2 = B_ * KOUT_;
    float* out_lab = (out_size >= 2 * n_val2) ? (out + n_val2) : nullptr;

    layer1_kernel<<<B_ * 16, 256>>>(inv, fidx, W1, b1);
    layer2_kernel<<<L2_GRID, 256>>>(lab, W2, b2, out, out_lab);
}

// round 8
// speedup vs baseline: 1.2269x; 1.2269x over previous
#include <cuda_runtime.h>
#include <cstddef>

#define B_      128
#define NNZ_    128
#define H_      128
#define KOUT_   4096
#define FDIM_   135909

// Intermediate val1 [B, H] — device global scratch (no allocations allowed).
__device__ float g_val1[B_ * H_];

// ---------------------------------------------------------------------------
// Layer 1: val1[b,h] = relu( sum_i v[b,i] * W1[h, fidx[b,i]] + b1[h] )
// Warp computes FOUR hidden units of one b (they share the gathered indices):
// each lane issues 16 independent 4B gathers (4 i's x 4 h's) before any FMA,
// -> ~440 outstanding sectors/SM (was ~220), lifting the latency-limited
// sector throughput from ~3.6 TB/s toward the pattern ceiling.
// Block = 8 warps = 32 h; grid = 128 b * 4 = 512 blocks.
// After the butterfly reduce EVERY lane holds the full sum for each hh, so
// the write is a statically-indexed predicated store (no shfl needed).
// ---------------------------------------------------------------------------
__global__ __launch_bounds__(256) void layer1_kernel(
    const float* __restrict__ inv,
    const int*   __restrict__ fidx,
    const float* __restrict__ W1,
    const float* __restrict__ b1)
{
    const int tid  = threadIdx.x;
    const int warp = tid >> 5;
    const int lane = tid & 31;
    const int b     = blockIdx.x >> 2;
    const int hbase = ((blockIdx.x & 3) << 5) + (warp << 2);   // 4 h per warp

    __shared__ int   sidx[NNZ_];
    __shared__ float sval[NNZ_];
    if (tid < 128) sidx[tid]       = fidx[(b << 7) + tid];
    else           sval[tid - 128] = inv [(b << 7) + tid - 128];
    __syncthreads();

    const int4   i4 = reinterpret_cast<const int4*>(sidx)[lane];
    const float4 v4 = reinterpret_cast<const float4*>(sval)[lane];

    // 16 independent gathers, all issued before any consumption
    float wv[16];
    #pragma unroll
    for (int hh = 0; hh < 4; hh++) {
        const float* w = W1 + (size_t)(hbase + hh) * FDIM_;
        wv[hh * 4 + 0] = __ldg(w + i4.x);
        wv[hh * 4 + 1] = __ldg(w + i4.y);
        wv[hh * 4 + 2] = __ldg(w + i4.z);
        wv[hh * 4 + 3] = __ldg(w + i4.w);
    }

    float acc[4];
    #pragma unroll
    for (int hh = 0; hh < 4; hh++)
        acc[hh] = wv[hh * 4 + 0] * v4.x + wv[hh * 4 + 1] * v4.y +
                  wv[hh * 4 + 2] * v4.z + wv[hh * 4 + 3] * v4.w;

    #pragma unroll
    for (int hh = 0; hh < 4; hh++) {
        #pragma unroll
        for (int o = 16; o > 0; o >>= 1)
            acc[hh] += __shfl_xor_sync(0xffffffffu, acc[hh], o);
    }

    // all lanes hold the reduced sums; lane hh writes unit hbase+hh
    #pragma unroll
    for (int hh = 0; hh < 4; hh++) {
        if (lane == hh)
            g_val1[(b << 7) + hbase + hh] =
                fmaxf(acc[hh] + __ldg(b1 + hbase + hh), 0.0f);
    }
}

// ---------------------------------------------------------------------------
// Layer 2 (exact R1 config — measured optimum at 41.9us / 68.3% DRAM):
//   val2[b,k] = <val1[b,:], W2[lab[b,k],:]> + b2[lab[b,k]]
// Warp = 4 outputs (4 coalesced 512B row loads in flight), block = 8 warps =
// 32 outputs of one b, val1[b] staged in smem. Grid = (B*KOUT)/32 = 16384.
// ---------------------------------------------------------------------------
__global__ __launch_bounds__(256) void layer2_kernel(
    const int*   __restrict__ lab,
    const float* __restrict__ W2,
    const float* __restrict__ b2,
    float*       __restrict__ out,
    float*       __restrict__ out_lab)   // may be null
{
    const int warp  = threadIdx.x >> 5;
    const int lane  = threadIdx.x & 31;
    const int b     = blockIdx.x >> 7;                      // 128 blocks per b
    const int kbase = ((blockIdx.x & 127) << 5) + (warp << 2);

    __shared__ float4 s4[32];
    if (threadIdx.x < 32)
        s4[threadIdx.x] = reinterpret_cast<const float4*>(g_val1 + (b << 7))[threadIdx.x];
    __syncthreads();

    const float4 sv = s4[lane];
    const int base = (b << 12) + kbase;

    int rows[4];
    #pragma unroll
    for (int j = 0; j < 4; j++) rows[j] = lab[base + j];

    float acc[4];
    #pragma unroll
    for (int j = 0; j < 4; j++) {
        const float4 wv = __ldg(reinterpret_cast<const float4*>(W2) +
                                ((size_t)rows[j] << 5) + lane);
        acc[j] = wv.x * sv.x + wv.y * sv.y + wv.z * sv.z + wv.w * sv.w;
    }

    #pragma unroll
    for (int j = 0; j < 4; j++) {
        #pragma unroll
        for (int o = 16; o > 0; o >>= 1)
            acc[j] += __shfl_xor_sync(0xffffffffu, acc[j], o);
    }

    if (lane < 4) {
        const int j = lane;
        const int r = rows[j];
        out[base + j] = acc[j] + __ldg(b2 + r);
        if (out_lab) out_lab[base + j] = (float)r;
    }
}

// ---------------------------------------------------------------------------
extern "C" void kernel_launch(void* const* d_in, const int* in_sizes, int n_in,
                              void* d_out, int out_size)
{
    const float* inv  = (const float*)d_in[0];   // in_values        [B, NNZ]
    const int*   fidx = (const int*)  d_in[1];   // active_in_indices[B, NNZ]
    const int*   lab  = (const int*)  d_in[2];   // active_label_idx [B, KOUT]
    const float* W1   = (const float*)d_in[3];   // [H, FDIM]
    const float* b1   = (const float*)d_in[4];   // [H]
    const float* W2   = (const float*)d_in[5];   // [C, H]
    const float* b2   = (const float*)d_in[6];   // [C]

    float* out = (float*)d_out;
    const int n_val2 = B_ * KOUT_;
    float* out_lab = (out_size >= 2 * n_val2) ? (out + n_val2) : nullptr;

    layer1_kernel<<<B_ * 4, 256>>>(inv, fidx, W1, b1);
    layer2_kernel<<<(B_ * KOUT_) / 32, 256>>>(lab, W2, b2, out, out_lab);
}